// round 5
// baseline (speedup 1.0000x reference)
#include <cuda_runtime.h>
#include <math.h>

#define TT  100
#define HH  50
#define ZZ  10
#define OUTD 65          // ZZ + ZZ*(ZZ+1)/2
#define NTRI 55          // ZZ*(ZZ+1)/2
#define LN_EPS 1e-6f

// scratch for hs (T x H) — __device__ global, no allocation
__device__ float g_hs[TT * HH];

// ---------------- packed f32x2 helpers (Blackwell) ----------------
__device__ __forceinline__ unsigned long long pk2(float lo, float hi) {
    unsigned long long r;
    asm("mov.b64 %0, {%1, %2};" : "=l"(r) : "f"(lo), "f"(hi));
    return r;
}
__device__ __forceinline__ void upk2(unsigned long long v, float& lo, float& hi) {
    asm("mov.b64 {%0, %1}, %2;" : "=f"(lo), "=f"(hi) : "l"(v));
}
__device__ __forceinline__ unsigned long long fma2(
    unsigned long long a, unsigned long long b, unsigned long long c) {
    unsigned long long d;
    asm("fma.rn.f32x2 %0, %1, %2, %3;" : "=l"(d) : "l"(a), "l"(b), "l"(c));
    return d;
}
__device__ __forceinline__ unsigned long long add2(
    unsigned long long a, unsigned long long b) {
    unsigned long long d;
    asm("add.rn.f32x2 %0, %1, %2;" : "=l"(d) : "l"(a), "l"(b));
    return d;
}

__device__ __forceinline__ float fast_sigmoid(float x) {
    float e = __expf(-x);
    return __fdividef(1.0f, 1.0f + e);
}
__device__ __forceinline__ float fast_tanh(float x) {
    float e = __expf(-2.0f * fabsf(x));
    float t = __fdividef(1.0f - e, 1.0f + e);
    return copysignf(t, x);
}

// ---------------------------------------------------------------------------
// Kernel 1: sequential GRU recurrence with layernormed gates.
// 96 threads = 3 warps, warp g owns gate g. Lane l owns columns 2l, 2l+1
// (active l < 25). Weight columns packed along i as f32x2 pairs in registers.
// h lives in shared; every lane broadcast-reloads the full h each step, so
// the matvec is 50 FFMA2 with NO shuffles. LN stats via one 5-step butterfly
// (two independent SHFLs per step). Two __syncthreads per step.
// ---------------------------------------------------------------------------
__global__ void __launch_bounds__(96, 1) gru_recurrence_kernel(
    const float* __restrict__ carry_init,
    const float* __restrict__ W_hr, const float* __restrict__ b_hr,
    const float* __restrict__ s_r,  const float* __restrict__ o_r,
    const float* __restrict__ W_hz, const float* __restrict__ b_hz,
    const float* __restrict__ s_z,  const float* __restrict__ o_z,
    const float* __restrict__ W_hn, const float* __restrict__ b_hn,
    const float* __restrict__ s_n,  const float* __restrict__ o_n)
{
    __shared__ __align__(8) float h_sh[HH];
    __shared__ float gate_sh[3][64];     // [gate][col] (padded rows)

    const int tid  = threadIdx.x;
    const int g    = tid >> 5;            // warp = gate, 0..2
    const int l    = tid & 31;            // lane
    const bool act = (l < 25);
    const int c0   = act ? 2 * l : 0;     // clamped for inactive lanes

    const float* Wg = (g == 0) ? W_hr : (g == 1) ? W_hz : W_hn;
    const float* bg = (g == 0) ? b_hr : (g == 1) ? b_hz : b_hn;
    const float* sg = (g == 0) ? s_r  : (g == 1) ? s_z  : s_n;
    const float* og = (g == 0) ? o_r  : (g == 1) ? o_z  : o_n;

    // Pack weights along i: wx[p] = (W[2p][c0], W[2p+1][c0]); wy for c0+1.
    unsigned long long wx[25], wy[25];
    #pragma unroll
    for (int p = 0; p < 25; p++) {
        const float* r0 = Wg + (2 * p)     * HH + c0;
        const float* r1 = Wg + (2 * p + 1) * HH + c0;
        wx[p] = pk2(r0[0], r1[0]);
        wy[p] = pk2(r0[1], r1[1]);
    }
    const float b0 = bg[c0], b1 = bg[c0 + 1];
    const float sc0 = sg[c0], sc1 = sg[c0 + 1];
    const float of0 = og[c0], of1 = og[c0 + 1];

    if (tid < HH) h_sh[tid] = carry_init[tid];
    __syncthreads();

    for (int t = 0; t < TT; t++) {
        // ---- broadcast-load full h as 25 packed 64-bit pairs (LDS.64 bcast)
        unsigned long long hu[25];
        #pragma unroll
        for (int p = 0; p < 25; p++) {
            double hd = reinterpret_cast<const double*>(h_sh)[p];
            hu[p] = __double_as_longlong(hd);
        }

        // ---- matvec: 50 FFMA2, 4 accumulators
        unsigned long long axe = 0ull, axo = 0ull, aye = 0ull, ayo = 0ull;
        #pragma unroll
        for (int p = 0; p < 25; p++) {
            if (p & 1) { axo = fma2(hu[p], wx[p], axo); ayo = fma2(hu[p], wy[p], ayo); }
            else       { axe = fma2(hu[p], wx[p], axe); aye = fma2(hu[p], wy[p], aye); }
        }
        float x0, x1, y0, y1;
        upk2(add2(axe, axo), x0, x1);
        upk2(add2(aye, ayo), y0, y1);
        float px = x0 + x1 + b0;
        float py = y0 + y1 + b1;

        // ---- in-warp layernorm stats: 5-step butterfly, 2 indep SHFL/step
        float sv = 0.f, qv = 0.f;
        if (act) { sv = px + py; qv = px * px + py * py; }
        #pragma unroll
        for (int off = 16; off; off >>= 1) {
            sv += __shfl_xor_sync(0xffffffffu, sv, off);
            qv += __shfl_xor_sync(0xffffffffu, qv, off);
        }
        float mean = sv * (1.0f / HH);
        float var  = qv * (1.0f / HH) - mean * mean;
        float inv  = rsqrtf(var + LN_EPS);

        float nx = (px - mean) * inv * sc0 + of0;
        float ny = (py - mean) * inv * sc1 + of1;

        float gx, gy;
        if (g < 2) { gx = fast_sigmoid(nx); gy = fast_sigmoid(ny); }
        else       { gx = nx;               gy = ny;               }

        if (act)
            *reinterpret_cast<float2*>(&gate_sh[g][c0]) = make_float2(gx, gy);
        __syncthreads();                                // BAR1: gates ready

        // ---- h update: one column per thread (threads 0..49)
        if (tid < HH) {
            float rr = gate_sh[0][tid];
            float zz = gate_sh[1][tid];
            float ln = gate_sh[2][tid];
            float n  = fast_tanh(rr * ln);
            float hn = zz * (h_sh[tid] - n) + n;        // (1-z)*n + z*h
            h_sh[tid] = hn;
            g_hs[t * HH + tid] = hn;
        }
        __syncthreads();                                // BAR2: h ready
    }
}

// ---------------------------------------------------------------------------
// Kernel 2: per-timestep dense + natural-parameter epilogue.
// One WARP per timestep: grid = 25 CTAs x 128 threads (4 warps = 4 t's).
// W_dense staged in shared once per CTA (coalesced); per-warp phases use
// __syncwarp only. Output layout: [Sigma T*Z*Z][mu T*Z][J T*Z*Z][h_nat T*Z]
// ---------------------------------------------------------------------------
__global__ void __launch_bounds__(128, 1) nat_kernel(
    const float* __restrict__ W_dense,
    const float* __restrict__ b_dense,
    float* __restrict__ out)
{
    __shared__ float Wsh[HH * OUTD];       // 3250 floats
    __shared__ float bsh[OUTD];
    __shared__ float osh [4][OUTD + 1];
    __shared__ float Lf  [4][NTRI + 1];    // lower-tri flat, softplus'd diag
    __shared__ float rdia[4][ZZ];
    __shared__ float Li  [4][ZZ][ZZ + 1];
    __shared__ float Js  [4][ZZ * ZZ + 1];

    const int tid  = threadIdx.x;
    const int w    = tid >> 5;
    const int lane = tid & 31;
    const int t    = blockIdx.x * 4 + w;   // 25*4 = 100, always valid

    // cooperative coalesced stage of W_dense (+ b)
    for (int k = tid; k < HH * OUTD; k += 128) Wsh[k] = W_dense[k];
    if (tid < OUTD) bsh[tid] = b_dense[tid];
    __syncthreads();

    // per-lane copy of this warp's h
    float hv[HH];
    {
        const float* hsrc = g_hs + t * HH;
        #pragma unroll
        for (int i = 0; i < HH; i++) hv[i] = __ldg(hsrc + i);
    }

    // dense: osh[o] = b[o] + sum_i h[i] * W[i][o]   (2-3 outputs per lane)
    for (int o = lane; o < OUTD; o += 32) {
        float a = bsh[o];
        #pragma unroll
        for (int i = 0; i < HH; i++)
            a = fmaf(hv[i], Wsh[i * OUTD + o], a);
        osh[w][o] = a;
    }
    __syncwarp();

    // build flat lower-triangular L; softplus on diagonal.
    // NTRI=55 > 32 lanes -> MUST stride (this was the R4 correctness bug).
    for (int k = lane; k < NTRI; k += 32) {
        int r = (int)((sqrtf(8.0f * k + 1.0f) - 1.0f) * 0.5f);
        int c = k - r * (r + 1) / 2;
        float v = osh[w][ZZ + k];
        if (c == r) {
            v = fmaxf(v, 0.0f) + log1pf(__expf(-fabsf(v)));
            rdia[w][r] = __fdividef(1.0f, v);
        }
        Lf[w][k] = v;
    }
    __syncwarp();

    const int SIG_OFF = 0;
    const int MU_OFF  = TT * ZZ * ZZ;
    const int J_OFF   = MU_OFF + TT * ZZ;
    const int HN_OFF  = J_OFF + TT * ZZ * ZZ;

    // mu
    if (lane < ZZ) out[MU_OFF + t * ZZ + lane] = osh[w][lane];

    // Sigma = L L^T
    for (int idx = lane; idx < ZZ * ZZ; idx += 32) {
        int i = idx / ZZ, jj = idx % ZZ;
        int m = (i < jj) ? i : jj;
        const float* Ri = &Lf[w][i  * (i  + 1) / 2];
        const float* Rj = &Lf[w][jj * (jj + 1) / 2];
        float sacc = 0.f;
        for (int k = 0; k <= m; k++) sacc = fmaf(Ri[k], Rj[k], sacc);
        out[SIG_OFF + t * ZZ * ZZ + idx] = sacc;
    }

    // L^{-1}: forward substitution, one column per lane (lane = column jc)
    if (lane < ZZ) {
        const int jc = lane;
        float x[ZZ];
        #pragma unroll
        for (int i = 0; i < ZZ; i++) {
            if (i < jc) { x[i] = 0.f; continue; }
            float s2 = (i == jc) ? 1.0f : 0.0f;
            const float* Ri = &Lf[w][i * (i + 1) / 2];
            #pragma unroll
            for (int k = 0; k < ZZ; k++)
                if (k >= jc && k < i) s2 -= Ri[k] * x[k];
            x[i] = s2 * rdia[w][i];
            Li[w][i][jc] = x[i];
        }
    }
    __syncwarp();

    // J = L^{-T} L^{-1} : J[i][j] = sum_{k>=max(i,j)} Li[k][i]*Li[k][j]
    for (int idx = lane; idx < ZZ * ZZ; idx += 32) {
        int i = idx / ZZ, jj = idx % ZZ;
        int m = (i > jj) ? i : jj;
        float sacc = 0.f;
        for (int k = m; k < ZZ; k++) sacc = fmaf(Li[w][k][i], Li[w][k][jj], sacc);
        Js[w][idx] = sacc;
        out[J_OFF + t * ZZ * ZZ + idx] = sacc;
    }
    __syncwarp();

    // h_nat = J @ mu
    if (lane < ZZ) {
        float sacc = 0.f;
        #pragma unroll
        for (int jj = 0; jj < ZZ; jj++)
            sacc = fmaf(Js[w][lane * ZZ + jj], osh[w][jj], sacc);
        out[HN_OFF + t * ZZ + lane] = sacc;
    }
}

// ---------------------------------------------------------------------------
// Launch. Input order (metadata): carry_init, W_hr, b_hr, s_r, o_r,
// W_hz, b_hz, s_z, o_z, W_hn, b_hn, s_n, o_n, W_dense, b_dense
// ---------------------------------------------------------------------------
extern "C" void kernel_launch(void* const* d_in, const int* in_sizes, int n_in,
                              void* d_out, int out_size)
{
    const float* carry   = (const float*)d_in[0];
    const float* W_hr    = (const float*)d_in[1];
    const float* b_hr    = (const float*)d_in[2];
    const float* s_r     = (const float*)d_in[3];
    const float* o_r     = (const float*)d_in[4];
    const float* W_hz    = (const float*)d_in[5];
    const float* b_hz    = (const float*)d_in[6];
    const float* s_z     = (const float*)d_in[7];
    const float* o_z     = (const float*)d_in[8];
    const float* W_hn    = (const float*)d_in[9];
    const float* b_hn    = (const float*)d_in[10];
    const float* s_n     = (const float*)d_in[11];
    const float* o_n     = (const float*)d_in[12];
    const float* W_dense = (const float*)d_in[13];
    const float* b_dense = (const float*)d_in[14];

    gru_recurrence_kernel<<<1, 96>>>(carry,
        W_hr, b_hr, s_r, o_r,
        W_hz, b_hz, s_z, o_z,
        W_hn, b_hn, s_n, o_n);

    nat_kernel<<<25, 128>>>(W_dense, b_dense, (float*)d_out);
}

// round 6
// speedup vs baseline: 1.4545x; 1.4545x over previous
#include <cuda_runtime.h>
#include <math.h>

#define TT  100
#define HH  50
#define ZZ  10
#define OUTD 65          // ZZ + ZZ*(ZZ+1)/2
#define NTRI 55          // ZZ*(ZZ+1)/2
#define LN_EPS 1e-6f
#define NTHREADS 96

// scratch for hs (T x H) + progress flag — __device__ globals, no allocation
__device__ float g_hs[TT * HH];
__device__ int   g_prog;          // monotone step counter (chunked)

__device__ __forceinline__ float fast_sigmoid(float x) {
    float e = __expf(-x);
    return __fdividef(1.0f, 1.0f + e);
}
__device__ __forceinline__ float fast_tanh(float x) {
    float e = __expf(-2.0f * fabsf(x));
    float t = __fdividef(1.0f - e, 1.0f + e);
    return copysignf(t, x);
}

// ---------------------------------------------------------------------------
// Recurrence (CTA 0): R2-proven design. 3 warps, warp g owns gate g.
// Lane l owns columns 2l, 2l+1 (active l < 25); weights in float2 registers;
// h in registers, broadcast by SHFL; ONE __syncthreads per step with
// parity-double-buffered gate exchange. g_hs stores split across 3 warps.
// Progress published every 10 steps (fence + flag).
// ---------------------------------------------------------------------------
__device__ __forceinline__ void recurrence_body(
    const float* __restrict__ carry_init,
    const float* __restrict__ W_hr, const float* __restrict__ b_hr,
    const float* __restrict__ s_r,  const float* __restrict__ o_r,
    const float* __restrict__ W_hz, const float* __restrict__ b_hz,
    const float* __restrict__ s_z,  const float* __restrict__ o_z,
    const float* __restrict__ W_hn, const float* __restrict__ b_hn,
    const float* __restrict__ s_n,  const float* __restrict__ o_n)
{
    __shared__ float gate_sh[2][3][64];   // [parity][gate][col] (padded rows)

    const int tid  = threadIdx.x;
    const int g    = tid >> 5;            // warp = gate, 0..2
    const int l    = tid & 31;            // lane
    const bool act = (l < 25);
    const int c0   = act ? 2 * l : 0;     // clamped for inactive lanes
    // g_hs store ownership: warp0 -> pairs 0-8, warp1 -> 9-16, warp2 -> 17-24
    const int owner = (l < 9) ? 0 : (l < 17) ? 1 : 2;

    const float* Wg = (g == 0) ? W_hr : (g == 1) ? W_hz : W_hn;
    const float* bg = (g == 0) ? b_hr : (g == 1) ? b_hz : b_hn;
    const float* sg = (g == 0) ? s_r  : (g == 1) ? s_z  : s_n;
    const float* og = (g == 0) ? o_r  : (g == 1) ? o_z  : o_n;

    // per-lane weight columns in registers: w[i] = (W[i][c0], W[i][c0+1])
    float2 w[HH];
    #pragma unroll
    for (int i = 0; i < HH; i++)
        w[i] = *reinterpret_cast<const float2*>(Wg + i * HH + c0);

    const float b0 = bg[c0], b1 = bg[c0 + 1];
    const float sc0 = sg[c0], sc1 = sg[c0 + 1];
    const float of0 = og[c0], of1 = og[c0 + 1];

    // h state in registers (lane l holds h[2l], h[2l+1])
    float h0 = carry_init[c0];
    float h1 = carry_init[c0 + 1];

    for (int t = 0; t < TT; t++) {
        // ---- matvec: acc = b + sum_i h[i] * W[i][c0..c0+1]
        float2 a[4];
        a[0] = make_float2(b0, b1);
        a[1] = make_float2(0.f, 0.f);
        a[2] = make_float2(0.f, 0.f);
        a[3] = make_float2(0.f, 0.f);
        #pragma unroll
        for (int i = 0; i < HH; i++) {
            float hv = __shfl_sync(0xffffffffu, (i & 1) ? h1 : h0, i >> 1);
            a[i & 3].x = fmaf(hv, w[i].x, a[i & 3].x);
            a[i & 3].y = fmaf(hv, w[i].y, a[i & 3].y);
        }
        float px = (a[0].x + a[1].x) + (a[2].x + a[3].x);
        float py = (a[0].y + a[1].y) + (a[2].y + a[3].y);

        // ---- in-warp layernorm stats over this gate's 50 columns
        float sv = 0.f, qv = 0.f;
        if (act) { sv = px + py; qv = px * px + py * py; }
        #pragma unroll
        for (int off = 16; off; off >>= 1) {
            sv += __shfl_xor_sync(0xffffffffu, sv, off);
            qv += __shfl_xor_sync(0xffffffffu, qv, off);
        }
        float mean = sv * (1.0f / HH);
        float var  = qv * (1.0f / HH) - mean * mean;
        float inv  = rsqrtf(var + LN_EPS);

        float nx = (px - mean) * inv * sc0 + of0;
        float ny = (py - mean) * inv * sc1 + of1;

        float gx, gy;
        if (g < 2) { gx = fast_sigmoid(nx); gy = fast_sigmoid(ny); }
        else       { gx = nx;               gy = ny;               }

        const int buf = t & 1;
        if (act)
            *reinterpret_cast<float2*>(&gate_sh[buf][g][c0]) = make_float2(gx, gy);
        __syncthreads();                       // the ONE barrier per step

        // publish progress for steps < t (their STGs precede this barrier)
        if (tid == 0 && t > 0 && (t % 10) == 0) {
            __threadfence();
            *(volatile int*)&g_prog = t;       // steps 0..t-1 ready
        }

        // ---- combine gates; every warp redundantly updates its h registers
        if (act) {
            float2 rv = *reinterpret_cast<float2*>(&gate_sh[buf][0][c0]);
            float2 zv = *reinterpret_cast<float2*>(&gate_sh[buf][1][c0]);
            float2 lv = *reinterpret_cast<float2*>(&gate_sh[buf][2][c0]);
            float n0 = fast_tanh(rv.x * lv.x);
            float n1 = fast_tanh(rv.y * lv.y);
            h0 = zv.x * (h0 - n0) + n0;        // (1-z)*n + z*h
            h1 = zv.y * (h1 - n1) + n1;
            if (g == owner)                    // split STG issue across warps
                *reinterpret_cast<float2*>(&g_hs[t * HH + c0]) = make_float2(h0, h1);
        }
    }

    __syncthreads();                           // all warps issued final STGs
    if (tid == 0) {
        __threadfence();
        *(volatile int*)&g_prog = TT;          // all steps ready
    }
}

// ---------------------------------------------------------------------------
// nat body (CTAs 1..100): R1-proven per-timestep epilogue, 96 threads.
// Output layout (fp32): [Sigma T*Z*Z][mu T*Z][J T*Z*Z][h_nat T*Z]
// ---------------------------------------------------------------------------
__device__ __forceinline__ void nat_body(
    int t,
    const float* __restrict__ W_dense,
    const float* __restrict__ b_dense,
    float* __restrict__ out)
{
    const int tid = threadIdx.x;

    __shared__ float hsh[HH];
    __shared__ float osh[OUTD];
    __shared__ float L   [ZZ][ZZ];
    __shared__ float rdia[ZZ];
    __shared__ float Li  [ZZ][ZZ];
    __shared__ float Jsh [ZZ][ZZ];

    // wait until the recurrence has published this timestep
    if (tid == 0) {
        while (*(volatile int*)&g_prog < t + 1) __nanosleep(64);
        __threadfence();
    }
    __syncthreads();

    if (tid < HH) hsh[tid] = g_hs[t * HH + tid];
    __syncthreads();

    // dense: out[o] = b[o] + sum_i hs[t][i] * W_dense[i][o]
    if (tid < OUTD) {
        float a = b_dense[tid];
        #pragma unroll
        for (int i = 0; i < HH; i++)
            a = fmaf(hsh[i], W_dense[i * OUTD + tid], a);
        osh[tid] = a;
    }
    __syncthreads();

    // build lower-triangular L from flat part; softplus on diagonal
    if (tid < NTRI) {                               // 55 < 96: single shot OK
        int k = tid;
        int r = (int)((sqrtf(8.0f * k + 1.0f) - 1.0f) * 0.5f);
        int c = k - r * (r + 1) / 2;
        float v = osh[ZZ + k];
        if (c == r) {
            v = fmaxf(v, 0.0f) + log1pf(__expf(-fabsf(v)));
            rdia[r] = __fdividef(1.0f, v);
        }
        L[r][c] = v;
    }
    __syncthreads();

    const int SIG_OFF = 0;
    const int MU_OFF  = TT * ZZ * ZZ;
    const int J_OFF   = MU_OFF + TT * ZZ;
    const int HN_OFF  = J_OFF + TT * ZZ * ZZ;

    // mu
    if (tid < ZZ) out[MU_OFF + t * ZZ + tid] = osh[tid];

    // Sigma = L L^T  (100 entries > 96 threads: stride)
    for (int idx = tid; idx < ZZ * ZZ; idx += NTHREADS) {
        int i = idx / ZZ, jj = idx % ZZ;
        int m = (i < jj) ? i : jj;
        float sacc = 0.f;
        for (int k = 0; k <= m; k++) sacc = fmaf(L[i][k], L[jj][k], sacc);
        out[SIG_OFF + t * ZZ * ZZ + idx] = sacc;
    }

    // L^{-1}: forward substitution, one column per thread (tid = column jc)
    if (tid < ZZ) {
        const int jc = tid;
        float x[ZZ];
        #pragma unroll
        for (int i = 0; i < ZZ; i++) {
            if (i < jc) { x[i] = 0.f; continue; }
            float s2 = (i == jc) ? 1.0f : 0.0f;
            #pragma unroll
            for (int k = 0; k < ZZ; k++)
                if (k >= jc && k < i) s2 -= L[i][k] * x[k];
            x[i] = s2 * rdia[i];
            Li[i][jc] = x[i];
        }
    }
    __syncthreads();

    // J = L^{-T} L^{-1} : J[i][j] = sum_{k>=max(i,j)} Li[k][i]*Li[k][j]
    for (int idx = tid; idx < ZZ * ZZ; idx += NTHREADS) {
        int i = idx / ZZ, jj = idx % ZZ;
        int m = (i > jj) ? i : jj;
        float sacc = 0.f;
        for (int k = m; k < ZZ; k++) sacc = fmaf(Li[k][i], Li[k][jj], sacc);
        Jsh[i][jj] = sacc;
        out[J_OFF + t * ZZ * ZZ + idx] = sacc;
    }
    __syncthreads();

    // h_nat = J @ mu
    if (tid < ZZ) {
        float sacc = 0.f;
        #pragma unroll
        for (int jj = 0; jj < ZZ; jj++)
            sacc = fmaf(Jsh[tid][jj], osh[jj], sacc);
        out[HN_OFF + t * ZZ + tid] = sacc;
    }
}

// ---------------------------------------------------------------------------
// Fused kernel: CTA 0 = recurrence producer; CTAs 1..100 = nat consumers.
// All 101 CTAs are co-resident (<= 148 SMs), so the spin-wait cannot deadlock.
// ---------------------------------------------------------------------------
__global__ void __launch_bounds__(NTHREADS, 1) gru_fused_kernel(
    const float* __restrict__ carry_init,
    const float* __restrict__ W_hr, const float* __restrict__ b_hr,
    const float* __restrict__ s_r,  const float* __restrict__ o_r,
    const float* __restrict__ W_hz, const float* __restrict__ b_hz,
    const float* __restrict__ s_z,  const float* __restrict__ o_z,
    const float* __restrict__ W_hn, const float* __restrict__ b_hn,
    const float* __restrict__ s_n,  const float* __restrict__ o_n,
    const float* __restrict__ W_dense,
    const float* __restrict__ b_dense,
    float* __restrict__ out)
{
    if (blockIdx.x == 0) {
        recurrence_body(carry_init,
                        W_hr, b_hr, s_r, o_r,
                        W_hz, b_hz, s_z, o_z,
                        W_hn, b_hn, s_n, o_n);
    } else {
        nat_body(blockIdx.x - 1, W_dense, b_dense, out);
    }
}

// ---------------------------------------------------------------------------
// Launch. Input order (metadata): carry_init, W_hr, b_hr, s_r, o_r,
// W_hz, b_hz, s_z, o_z, W_hn, b_hn, s_n, o_n, W_dense, b_dense
// ---------------------------------------------------------------------------
extern "C" void kernel_launch(void* const* d_in, const int* in_sizes, int n_in,
                              void* d_out, int out_size)
{
    const float* carry   = (const float*)d_in[0];
    const float* W_hr    = (const float*)d_in[1];
    const float* b_hr    = (const float*)d_in[2];
    const float* s_r     = (const float*)d_in[3];
    const float* o_r     = (const float*)d_in[4];
    const float* W_hz    = (const float*)d_in[5];
    const float* b_hz    = (const float*)d_in[6];
    const float* s_z     = (const float*)d_in[7];
    const float* o_z     = (const float*)d_in[8];
    const float* W_hn    = (const float*)d_in[9];
    const float* b_hn    = (const float*)d_in[10];
    const float* s_n     = (const float*)d_in[11];
    const float* o_n     = (const float*)d_in[12];
    const float* W_dense = (const float*)d_in[13];
    const float* b_dense = (const float*)d_in[14];

    gru_fused_kernel<<<1 + TT, NTHREADS>>>(carry,
        W_hr, b_hr, s_r, o_r,
        W_hz, b_hz, s_z, o_z,
        W_hn, b_hn, s_n, o_n,
        W_dense, b_dense, (float*)d_out);
}